// round 13
// baseline (speedup 1.0000x reference)
#include <cuda_runtime.h>
#include <cuda_fp16.h>

#define NN 100000
#define EE 1000000
#define HH 64
#define GG 512
#define CC 2

#define SCAN_T 512
#define SCAN_NB ((NN + SCAN_T - 1) / SCAN_T)   // 196
#define FIXS 16777216.0f                       // 2^24 fixed-point scale
#define FIXMASK ((1ull << 44) - 1)

#define FILL_B ((EE + 255) / 256)              // 3907 fill blocks
#define GEMM_B ((NN + 63) / 64)                // 1563 gemm blocks

// Scratch (device globals; no allocations allowed)
__device__ __half g_bufA[NN * HH];
__device__ __half g_bufB[NN * HH];
__device__ float g_y[NN * CC];
__device__ float g_dinv[NN];
__device__ unsigned long long g_degcnt[NN];   // count<<44 | wsum*2^24
__device__ int   g_fill[NN];
__device__ int   g_rowptr[NN + 1];
__device__ int2  g_cmeta[EE];                 // (src, norm bits)
__device__ float g_cnt[GG];
__device__ float g_plog[GG * CC];
__device__ float g_M[HH * CC];                // W3 @ Wl
__device__ float g_bWl[CC];                   // b3 @ Wl
__device__ int   g_bsum[SCAN_NB];
__device__ int   g_boff[SCAN_NB];

// ---------------------------------------------------------------------------
__global__ __launch_bounds__(256) void k_zero(const float* __restrict__ W3,
                                              const float* __restrict__ Wl,
                                              const float* __restrict__ b3) {
    int i = blockIdx.x * blockDim.x + threadIdx.x;
    if (i < NN) { g_degcnt[i] = 0ull; g_fill[i] = 0; }
    if (i < GG) g_cnt[i] = 0.f;
    if (i < GG * CC) g_plog[i] = 0.f;
    if (blockIdx.x == 0) {
        int t = threadIdx.x;
        if (t < HH * CC) {
            int k = t >> 1, c = t & 1;
            float acc = 0.f;
#pragma unroll
            for (int j = 0; j < HH; j++) acc += W3[k * HH + j] * Wl[j * CC + c];
            g_M[t] = acc;
        } else if (t < HH * CC + CC) {
            int c = t - HH * CC;
            float acc = 0.f;
#pragma unroll
            for (int j = 0; j < HH; j++) acc += b3[j] * Wl[j * CC + c];
            g_bWl[c] = acc;
        }
    }
}

// degree pass: one packed 64-bit atomic per edge
__global__ __launch_bounds__(256) void k_deg(const int* __restrict__ dst,
                                             const float* __restrict__ w) {
    int e = blockIdx.x * blockDim.x + threadIdx.x;
    if (e < EE) {
        unsigned long long val =
            (1ull << 44) | (unsigned long long)(w[e] * FIXS);
        atomicAdd(&g_degcnt[dst[e]], val);
    }
}

// scanA + dinv + graph node count (fused)
__global__ __launch_bounds__(SCAN_T) void k_scanA(const int* __restrict__ batch) {
    __shared__ int sh[SCAN_T / 32];
    int b = blockIdx.x, t = threadIdx.x;
    int i = b * SCAN_T + t;
    unsigned long long pv = (i < NN) ? g_degcnt[i] : 0ull;
    int v = (int)(pv >> 44);
    if (i < NN) {
        float deg = (float)((double)(pv & FIXMASK) * (1.0 / 16777216.0));
        g_dinv[i] = rsqrtf(deg + 2.0f);
        atomicAdd(&g_cnt[batch[i]], 1.0f);
    }
    int s = v;
#pragma unroll
    for (int off = 16; off; off >>= 1) s += __shfl_xor_sync(~0u, s, off);
    if ((t & 31) == 0) sh[t >> 5] = s;
    __syncthreads();
    if (t < SCAN_T / 32) {
        int r = sh[t];
#pragma unroll
        for (int off = SCAN_T / 64; off; off >>= 1)
            r += __shfl_xor_sync(0xffffu, r, off);
        if (t == 0) g_bsum[b] = r;
    }
}

__global__ __launch_bounds__(256) void k_scanB() {
    __shared__ int sh[256];
    int t = threadIdx.x;
    int v = (t < SCAN_NB) ? g_bsum[t] : 0;
    sh[t] = v;
    __syncthreads();
    for (int off = 1; off < 256; off <<= 1) {
        int u = (t >= off) ? sh[t - off] : 0;
        __syncthreads();
        sh[t] += u;
        __syncthreads();
    }
    if (t < SCAN_NB) g_boff[t] = sh[t] - v;
    if (t == 255) g_rowptr[NN] = sh[255];
}

__global__ __launch_bounds__(SCAN_T) void k_scanC() {
    __shared__ int sh[SCAN_T];
    int b = blockIdx.x, t = threadIdx.x;
    int i = b * SCAN_T + t;
    int v = (i < NN) ? (int)(g_degcnt[i] >> 44) : 0;
    sh[t] = v;
    __syncthreads();
    for (int off = 1; off < SCAN_T; off <<= 1) {
        int u = (t >= off) ? sh[t - off] : 0;
        __syncthreads();
        sh[t] += u;
        __syncthreads();
    }
    if (i < NN) g_rowptr[i] = g_boff[b] + sh[t] - v;
}

// ---------------------------------------------------------------------------
// Warp-level gather of one node's aggregated row from fp16 xw (2 cols/lane).
__device__ __forceinline__ void gather_node(const __half* __restrict__ xw,
                                            int n, int lane,
                                            const float* __restrict__ bias,
                                            float& a0, float& a1) {
    int beg = g_rowptr[n], end = g_rowptr[n + 1];
    float b0 = 0.f, b1 = 0.f, c0 = 0.f, c1 = 0.f, d0 = 0.f, d1 = 0.f;
    a0 = 0.f; a1 = 0.f;
    for (int cb = beg; cb < end; cb += 32) {
        int m = end - cb; if (m > 32) m = 32;
        int sreg = 0; float vreg = 0.f;
        if (lane < m) {
            int2 mv = g_cmeta[cb + lane];
            sreg = mv.x; vreg = __int_as_float(mv.y);
        }
        int j = 0;
        for (; j + 3 < m; j += 4) {
            int s0 = __shfl_sync(~0u, sreg, j);
            int s1 = __shfl_sync(~0u, sreg, j + 1);
            int s2 = __shfl_sync(~0u, sreg, j + 2);
            int s3 = __shfl_sync(~0u, sreg, j + 3);
            float v0 = __shfl_sync(~0u, vreg, j);
            float v1 = __shfl_sync(~0u, vreg, j + 1);
            float v2 = __shfl_sync(~0u, vreg, j + 2);
            float v3 = __shfl_sync(~0u, vreg, j + 3);
            float2 x0 = __half22float2(*(const __half2*)(xw + (size_t)s0 * 64 + lane * 2));
            float2 x1 = __half22float2(*(const __half2*)(xw + (size_t)s1 * 64 + lane * 2));
            float2 x2 = __half22float2(*(const __half2*)(xw + (size_t)s2 * 64 + lane * 2));
            float2 x3 = __half22float2(*(const __half2*)(xw + (size_t)s3 * 64 + lane * 2));
            a0 += v0 * x0.x; a1 += v0 * x0.y;
            b0 += v1 * x1.x; b1 += v1 * x1.y;
            c0 += v2 * x2.x; c1 += v2 * x2.y;
            d0 += v3 * x3.x; d1 += v3 * x3.y;
        }
        for (; j < m; j++) {
            int s = __shfl_sync(~0u, sreg, j);
            float v = __shfl_sync(~0u, vreg, j);
            float2 xv = __half22float2(*(const __half2*)(xw + (size_t)s * 64 + lane * 2));
            a0 += v * xv.x; a1 += v * xv.y;
        }
    }
    a0 += b0 + c0; a0 += d0;
    a1 += b1 + c1; a1 += d1;
    float di = g_dinv[n];
    float sl = 2.0f * di * di;
    float2 xwn = __half22float2(*(const __half2*)(xw + (size_t)n * 64 + lane * 2));
    a0 += sl * xwn.x + bias[lane * 2 + 0];
    a1 += sl * xwn.y + bias[lane * 2 + 1];
}

__device__ __forceinline__ void store_h4(__half* __restrict__ out, size_t off,
                                         float a, float b, float c, float d) {
    __half2 h01 = __floats2half2_rn(a, b);
    __half2 h23 = __floats2half2_rn(c, d);
    uint2 pk;
    pk.x = *reinterpret_cast<unsigned*>(&h01);
    pk.y = *reinterpret_cast<unsigned*>(&h23);
    *reinterpret_cast<uint2*>(out + off) = pk;
}

// ---------------------------------------------------------------------------
// Heterogeneous kernel: blocks [0,FILL_B) fill CSR; blocks [FILL_B,..) do
// layer-1 GEMM (xw1 = x @ W1 -> fp16).  The two are independent.
__global__ __launch_bounds__(256) void k_fillgemm(const int* __restrict__ src,
                                                  const int* __restrict__ dst,
                                                  const float* __restrict__ w,
                                                  const float* __restrict__ in,
                                                  const float* __restrict__ W,
                                                  __half* __restrict__ out) {
    __shared__ float Ws[64 * 64];
    __shared__ float XsT[64][65];
    int tid = threadIdx.x;
    if (blockIdx.x < FILL_B) {
        int e = blockIdx.x * 256 + tid;
        if (e < EE) {
            int s = src[e], d = dst[e];
            float nrm = g_dinv[s] * w[e] * g_dinv[d];
            int pos = g_rowptr[d] + atomicAdd(&g_fill[d], 1);
            g_cmeta[pos] = make_int2(s, __float_as_int(nrm));
        }
        return;
    }
    int base = (blockIdx.x - FILL_B) * 64;
    for (int i = tid; i < 4096; i += 256) Ws[i] = W[i];
    for (int idx = tid; idx < 4096; idx += 256) {
        int r = idx >> 6, c = idx & 63;
        int row = base + r;
        XsT[c][r] = (row < NN) ? in[row * 64 + c] : 0.f;
    }
    __syncthreads();
    int tr = tid >> 4, tc = tid & 15;
    float acc[4][4] = {};
#pragma unroll
    for (int k = 0; k < 64; k++) {
        float x0 = XsT[k][tr * 4 + 0];
        float x1 = XsT[k][tr * 4 + 1];
        float x2 = XsT[k][tr * 4 + 2];
        float x3 = XsT[k][tr * 4 + 3];
        float4 wv = *(const float4*)&Ws[k * 64 + tc * 4];
        acc[0][0] += x0 * wv.x; acc[0][1] += x0 * wv.y;
        acc[0][2] += x0 * wv.z; acc[0][3] += x0 * wv.w;
        acc[1][0] += x1 * wv.x; acc[1][1] += x1 * wv.y;
        acc[1][2] += x1 * wv.z; acc[1][3] += x1 * wv.w;
        acc[2][0] += x2 * wv.x; acc[2][1] += x2 * wv.y;
        acc[2][2] += x2 * wv.z; acc[2][3] += x2 * wv.w;
        acc[3][0] += x3 * wv.x; acc[3][1] += x3 * wv.y;
        acc[3][2] += x3 * wv.z; acc[3][3] += x3 * wv.w;
    }
#pragma unroll
    for (int i = 0; i < 4; i++) {
        int row = base + tr * 4 + i;
        if (row < NN)
            store_h4(out, (size_t)row * 64 + tc * 4,
                     acc[i][0], acc[i][1], acc[i][2], acc[i][3]);
    }
}

// ---------------------------------------------------------------------------
// Fused: h = relu(agg(xw_in)+self+bias); xw_out(fp16) = h @ W.
__global__ __launch_bounds__(256) void k_fused(const __half* __restrict__ xw_in,
                                               __half* __restrict__ xw_out,
                                               const float* __restrict__ bias,
                                               const float* __restrict__ W) {
    __shared__ float Ws[64 * 64];
    __shared__ float XsT[64][65];
    int tid = threadIdx.x;
    int wrp = tid >> 5, lane = tid & 31;
    int base = blockIdx.x * 64;
    for (int i = tid; i < 4096; i += 256) Ws[i] = W[i];
#pragma unroll 1
    for (int i = 0; i < 8; i++) {
        int r = wrp * 8 + i;
        int n = base + r;
        float a0 = 0.f, a1 = 0.f;
        if (n < NN) gather_node(xw_in, n, lane, bias, a0, a1);
        XsT[lane * 2 + 0][r] = fmaxf(a0, 0.f);
        XsT[lane * 2 + 1][r] = fmaxf(a1, 0.f);
    }
    __syncthreads();
    int tr = tid >> 4, tc = tid & 15;
    float acc[4][4] = {};
#pragma unroll
    for (int k = 0; k < 64; k++) {
        float x0 = XsT[k][tr * 4 + 0];
        float x1 = XsT[k][tr * 4 + 1];
        float x2 = XsT[k][tr * 4 + 2];
        float x3 = XsT[k][tr * 4 + 3];
        float4 wv = *(const float4*)&Ws[k * 64 + tc * 4];
        acc[0][0] += x0 * wv.x; acc[0][1] += x0 * wv.y;
        acc[0][2] += x0 * wv.z; acc[0][3] += x0 * wv.w;
        acc[1][0] += x1 * wv.x; acc[1][1] += x1 * wv.y;
        acc[1][2] += x1 * wv.z; acc[1][3] += x1 * wv.w;
        acc[2][0] += x2 * wv.x; acc[2][1] += x2 * wv.y;
        acc[2][2] += x2 * wv.z; acc[2][3] += x2 * wv.w;
        acc[3][0] += x3 * wv.x; acc[3][1] += x3 * wv.y;
        acc[3][2] += x3 * wv.z; acc[3][3] += x3 * wv.w;
    }
#pragma unroll
    for (int i = 0; i < 4; i++) {
        int row = base + tr * 4 + i;
        if (row < NN)
            store_h4(xw_out, (size_t)row * 64 + tc * 4,
                     acc[i][0], acc[i][1], acc[i][2], acc[i][3]);
    }
}

// ---------------------------------------------------------------------------
// Layer-3 reduced: h2 = relu(agg+self+b2); y = h2 @ M (64x2)
__global__ __launch_bounds__(256) void k_fused_y(const __half* __restrict__ xw_in,
                                                 const float* __restrict__ bias) {
    int wid = (blockIdx.x * blockDim.x + threadIdx.x) >> 5;
    int lane = threadIdx.x & 31;
    if (wid >= NN) return;
    float a0, a1;
    gather_node(xw_in, wid, lane, bias, a0, a1);
    a0 = fmaxf(a0, 0.f);
    a1 = fmaxf(a1, 0.f);
    int j0 = lane * 2, j1 = lane * 2 + 1;
    float y0 = a0 * g_M[j0 * CC + 0] + a1 * g_M[j1 * CC + 0];
    float y1 = a0 * g_M[j0 * CC + 1] + a1 * g_M[j1 * CC + 1];
#pragma unroll
    for (int off = 16; off; off >>= 1) {
        y0 += __shfl_xor_sync(0xffffffffu, y0, off);
        y1 += __shfl_xor_sync(0xffffffffu, y1, off);
    }
    if (lane == 0) *(float2*)&g_y[wid * CC] = make_float2(y0, y1);
}

// ---------------------------------------------------------------------------
// Edge pass in y-space + pool.
__global__ __launch_bounds__(256) void k_edge(const int* __restrict__ batch) {
    int wid = (blockIdx.x * blockDim.x + threadIdx.x) >> 5;
    int lane = threadIdx.x & 31;
    if (wid >= NN) return;
    int n = wid;
    int beg = g_rowptr[n], end = g_rowptr[n + 1];
    float l0 = 0.f, l1 = 0.f;
    for (int cb = beg + lane; cb < end; cb += 32) {
        int2 mv = g_cmeta[cb];
        float v = __int_as_float(mv.y);
        float2 yv = *(const float2*)&g_y[mv.x * CC];
        l0 += v * yv.x;
        l1 += v * yv.y;
    }
#pragma unroll
    for (int off = 16; off; off >>= 1) {
        l0 += __shfl_xor_sync(0xffffffffu, l0, off);
        l1 += __shfl_xor_sync(0xffffffffu, l1, off);
    }
    if (lane == 0) {
        float di = g_dinv[n];
        float sl = 2.0f * di * di;
        float2 yn = *(const float2*)&g_y[n * CC];
        l0 += sl * yn.x;
        l1 += sl * yn.y;
        int g = batch[n];
        atomicAdd(&g_plog[g * CC + 0], l0);
        atomicAdd(&g_plog[g * CC + 1], l1);
    }
}

__global__ __launch_bounds__(256) void k_final(const float* __restrict__ bl,
                                               float* __restrict__ out) {
    int i = blockIdx.x * blockDim.x + threadIdx.x;
    if (i < GG * CC) {
        int g = i / CC, c = i % CC;
        float cnt = g_cnt[g];
        out[i] = (cnt > 0.f) ? g_plog[i] / cnt + g_bWl[c] + bl[c] : bl[c];
    }
}

extern "C" void kernel_launch(void* const* d_in, const int* in_sizes, int n_in,
                              void* d_out, int out_size) {
    const float* x     = (const float*)d_in[0];
    const int*   ei    = (const int*)d_in[1];
    const float* w     = (const float*)d_in[2];
    const int*   batch = (const int*)d_in[3];
    const float* W1    = (const float*)d_in[4];
    const float* b1    = (const float*)d_in[5];
    const float* W2    = (const float*)d_in[6];
    const float* b2    = (const float*)d_in[7];
    const float* W3    = (const float*)d_in[8];
    const float* b3    = (const float*)d_in[9];
    const float* Wl    = (const float*)d_in[10];
    const float* bl    = (const float*)d_in[11];
    float* out = (float*)d_out;

    const int* src = ei;
    const int* dst = ei + EE;

    __half* A;  cudaGetSymbolAddress((void**)&A, g_bufA);
    __half* B;  cudaGetSymbolAddress((void**)&B, g_bufB);

    const int eb = (EE + 255) / 256;
    const int nb = (NN + 255) / 256;
    const int warp_b = (NN * 32 + 255) / 256;

    // CSR + normalization build
    k_zero<<<nb, 256>>>(W3, Wl, b3);
    k_deg<<<eb, 256>>>(dst, w);
    k_scanA<<<SCAN_NB, SCAN_T>>>(batch);
    k_scanB<<<1, 256>>>();
    k_scanC<<<SCAN_NB, SCAN_T>>>();

    // CSR fill + layer-1 GEMM overlapped (independent work)
    k_fillgemm<<<FILL_B + GEMM_B, 256>>>(src, dst, w, x, W1, A);

    // layer 2 fused: h1 = relu(agg(A)+b1); xw2 = h1 @ W2 -> B (fp16)
    k_fused<<<GEMM_B, 256>>>(A, B, b1, W2);
    // layer 3 reduced: h2 = relu(agg(B)+b2); y = h2 @ (W3@Wl)
    k_fused_y<<<warp_b, 256>>>(B, b2);
    // edge pass in y-space + pool
    k_edge<<<warp_b, 256>>>(batch);

    k_final<<<(GG * CC + 255) / 256, 256>>>(bl, out);
}

// round 16
// speedup vs baseline: 1.0553x; 1.0553x over previous
#include <cuda_runtime.h>
#include <cuda_fp16.h>

#define NN 100000
#define EE 1000000
#define HH 64
#define GG 512
#define CC 2

#define SCAN_T 512
#define SCAN_NB ((NN + SCAN_T - 1) / SCAN_T)   // 196

// Scratch (device globals; no allocations allowed)
__device__ __half g_bufA[NN * HH];
__device__ __half g_bufB[NN * HH];
__device__ float g_y[NN * CC];
__device__ float g_dinv[NN];
__device__ float g_deg[NN];
__device__ int   g_ecnt[NN];
__device__ int   g_fill[NN];
__device__ int   g_rowptr[NN + 1];
__device__ int2  g_cmeta[EE];                 // (src, norm bits)
__device__ float g_cnt[GG];
__device__ float g_plog[GG * CC];
__device__ float g_M[HH * CC];                // W3 @ Wl
__device__ float g_bWl[CC];                   // b3 @ Wl
__device__ int   g_bsum[SCAN_NB];

// ---------------------------------------------------------------------------
__global__ __launch_bounds__(256) void k_zero(const float* __restrict__ W3,
                                              const float* __restrict__ Wl,
                                              const float* __restrict__ b3) {
    int i = blockIdx.x * blockDim.x + threadIdx.x;
    if (i < NN) { g_deg[i] = 0.f; g_ecnt[i] = 0; g_fill[i] = 0; }
    if (i < GG) g_cnt[i] = 0.f;
    if (i < GG * CC) g_plog[i] = 0.f;
    if (i == 0) g_rowptr[NN] = EE;            // constant: total edges
    if (blockIdx.x == 0) {
        int t = threadIdx.x;
        if (t < HH * CC) {
            int k = t >> 1, c = t & 1;
            float acc = 0.f;
#pragma unroll
            for (int j = 0; j < HH; j++) acc += W3[k * HH + j] * Wl[j * CC + c];
            g_M[t] = acc;
        } else if (t < HH * CC + CC) {
            int c = t - HH * CC;
            float acc = 0.f;
#pragma unroll
            for (int j = 0; j < HH; j++) acc += b3[j] * Wl[j * CC + c];
            g_bWl[c] = acc;
        }
    }
}

__global__ __launch_bounds__(256) void k_deg(const int* __restrict__ dst,
                                             const float* __restrict__ w) {
    int e = blockIdx.x * blockDim.x + threadIdx.x;
    if (e < EE) {
        int d = dst[e];
        atomicAdd(&g_deg[d], w[e]);
        atomicAdd(&g_ecnt[d], 1);
    }
}

// scanA + dinv + graph node count (fused)
__global__ __launch_bounds__(SCAN_T) void k_scanA(const int* __restrict__ batch) {
    __shared__ int sh[SCAN_T / 32];
    int b = blockIdx.x, t = threadIdx.x;
    int i = b * SCAN_T + t;
    int v = (i < NN) ? g_ecnt[i] : 0;
    if (i < NN) {
        g_dinv[i] = rsqrtf(g_deg[i] + 2.0f);
        atomicAdd(&g_cnt[batch[i]], 1.0f);
    }
    int s = v;
#pragma unroll
    for (int off = 16; off; off >>= 1) s += __shfl_xor_sync(~0u, s, off);
    if ((t & 31) == 0) sh[t >> 5] = s;
    __syncthreads();
    if (t < SCAN_T / 32) {
        int r = sh[t];
#pragma unroll
        for (int off = SCAN_T / 64; off; off >>= 1)
            r += __shfl_xor_sync(0xffffu, r, off);
        if (t == 0) g_bsum[b] = r;
    }
}

// scanC: per-block offset computed in-block from g_bsum, then local scan.
__global__ __launch_bounds__(SCAN_T) void k_scanC() {
    __shared__ int sh[SCAN_T];
    int b = blockIdx.x, t = threadIdx.x;
    // phase 1: inclusive scan of the 196 block sums
    int bs = (t < SCAN_NB) ? g_bsum[t] : 0;
    sh[t] = bs;
    __syncthreads();
    for (int off = 1; off < SCAN_T; off <<= 1) {
        int u = (t >= off) ? sh[t - off] : 0;
        __syncthreads();
        sh[t] += u;
        __syncthreads();
    }
    int boff = sh[b] - g_bsum[b];             // exclusive offset of this block
    __syncthreads();
    // phase 2: local exclusive scan of ecnt
    int i = b * SCAN_T + t;
    int v = (i < NN) ? g_ecnt[i] : 0;
    sh[t] = v;
    __syncthreads();
    for (int off = 1; off < SCAN_T; off <<= 1) {
        int u = (t >= off) ? sh[t - off] : 0;
        __syncthreads();
        sh[t] += u;
        __syncthreads();
    }
    if (i < NN) g_rowptr[i] = boff + sh[t] - v;
}

__global__ __launch_bounds__(256) void k_fill(const int* __restrict__ src,
                                              const int* __restrict__ dst,
                                              const float* __restrict__ w) {
    int e = blockIdx.x * blockDim.x + threadIdx.x;
    if (e < EE) {
        int s = src[e], d = dst[e];
        float nrm = g_dinv[s] * w[e] * g_dinv[d];
        int pos = g_rowptr[d] + atomicAdd(&g_fill[d], 1);
        g_cmeta[pos] = make_int2(s, __float_as_int(nrm));
    }
}

// ---------------------------------------------------------------------------
// Warp-level gather of one node's aggregated row from fp16 xw (2 cols/lane).
__device__ __forceinline__ void gather_node(const __half* __restrict__ xw,
                                            int n, int lane,
                                            const float* __restrict__ bias,
                                            float& a0, float& a1) {
    int beg = g_rowptr[n], end = g_rowptr[n + 1];
    float b0 = 0.f, b1 = 0.f, c0 = 0.f, c1 = 0.f, d0 = 0.f, d1 = 0.f;
    a0 = 0.f; a1 = 0.f;
    for (int cb = beg; cb < end; cb += 32) {
        int m = end - cb; if (m > 32) m = 32;
        int sreg = 0; float vreg = 0.f;
        if (lane < m) {
            int2 mv = g_cmeta[cb + lane];
            sreg = mv.x; vreg = __int_as_float(mv.y);
        }
        int j = 0;
        for (; j + 3 < m; j += 4) {
            int s0 = __shfl_sync(~0u, sreg, j);
            int s1 = __shfl_sync(~0u, sreg, j + 1);
            int s2 = __shfl_sync(~0u, sreg, j + 2);
            int s3 = __shfl_sync(~0u, sreg, j + 3);
            float v0 = __shfl_sync(~0u, vreg, j);
            float v1 = __shfl_sync(~0u, vreg, j + 1);
            float v2 = __shfl_sync(~0u, vreg, j + 2);
            float v3 = __shfl_sync(~0u, vreg, j + 3);
            float2 x0 = __half22float2(*(const __half2*)(xw + (size_t)s0 * 64 + lane * 2));
            float2 x1 = __half22float2(*(const __half2*)(xw + (size_t)s1 * 64 + lane * 2));
            float2 x2 = __half22float2(*(const __half2*)(xw + (size_t)s2 * 64 + lane * 2));
            float2 x3 = __half22float2(*(const __half2*)(xw + (size_t)s3 * 64 + lane * 2));
            a0 += v0 * x0.x; a1 += v0 * x0.y;
            b0 += v1 * x1.x; b1 += v1 * x1.y;
            c0 += v2 * x2.x; c1 += v2 * x2.y;
            d0 += v3 * x3.x; d1 += v3 * x3.y;
        }
        for (; j < m; j++) {
            int s = __shfl_sync(~0u, sreg, j);
            float v = __shfl_sync(~0u, vreg, j);
            float2 xv = __half22float2(*(const __half2*)(xw + (size_t)s * 64 + lane * 2));
            a0 += v * xv.x; a1 += v * xv.y;
        }
    }
    a0 += b0 + c0; a0 += d0;
    a1 += b1 + c1; a1 += d1;
    float di = g_dinv[n];
    float sl = 2.0f * di * di;
    float2 xwn = __half22float2(*(const __half2*)(xw + (size_t)n * 64 + lane * 2));
    a0 += sl * xwn.x + bias[lane * 2 + 0];
    a1 += sl * xwn.y + bias[lane * 2 + 1];
}

__device__ __forceinline__ void store_h4(__half* __restrict__ out, size_t off,
                                         float a, float b, float c, float d) {
    __half2 h01 = __floats2half2_rn(a, b);
    __half2 h23 = __floats2half2_rn(c, d);
    uint2 pk;
    pk.x = *reinterpret_cast<unsigned*>(&h01);
    pk.y = *reinterpret_cast<unsigned*>(&h23);
    *reinterpret_cast<uint2*>(out + off) = pk;
}

// ---------------------------------------------------------------------------
// Layer-1 GEMM: out(fp16) = in @ W.
__global__ __launch_bounds__(256) void k_gemm64(const float* __restrict__ in,
                                                const float* __restrict__ W,
                                                __half* __restrict__ out) {
    __shared__ float Ws[64 * 64];
    __shared__ float XsT[64][65];
    int tid = threadIdx.x;
    int base = blockIdx.x * 64;
    for (int i = tid; i < 4096; i += 256) Ws[i] = W[i];
    for (int idx = tid; idx < 4096; idx += 256) {
        int r = idx >> 6, c = idx & 63;
        int row = base + r;
        XsT[c][r] = (row < NN) ? in[row * 64 + c] : 0.f;
    }
    __syncthreads();
    int tr = tid >> 4, tc = tid & 15;
    float acc[4][4] = {};
#pragma unroll
    for (int k = 0; k < 64; k++) {
        float x0 = XsT[k][tr * 4 + 0];
        float x1 = XsT[k][tr * 4 + 1];
        float x2 = XsT[k][tr * 4 + 2];
        float x3 = XsT[k][tr * 4 + 3];
        float4 wv = *(const float4*)&Ws[k * 64 + tc * 4];
        acc[0][0] += x0 * wv.x; acc[0][1] += x0 * wv.y;
        acc[0][2] += x0 * wv.z; acc[0][3] += x0 * wv.w;
        acc[1][0] += x1 * wv.x; acc[1][1] += x1 * wv.y;
        acc[1][2] += x1 * wv.z; acc[1][3] += x1 * wv.w;
        acc[2][0] += x2 * wv.x; acc[2][1] += x2 * wv.y;
        acc[2][2] += x2 * wv.z; acc[2][3] += x2 * wv.w;
        acc[3][0] += x3 * wv.x; acc[3][1] += x3 * wv.y;
        acc[3][2] += x3 * wv.z; acc[3][3] += x3 * wv.w;
    }
#pragma unroll
    for (int i = 0; i < 4; i++) {
        int row = base + tr * 4 + i;
        if (row < NN)
            store_h4(out, (size_t)row * 64 + tc * 4,
                     acc[i][0], acc[i][1], acc[i][2], acc[i][3]);
    }
}

// ---------------------------------------------------------------------------
// Fused: h = relu(agg(xw_in)+self+bias); xw_out(fp16) = h @ W.
__global__ __launch_bounds__(256) void k_fused(const __half* __restrict__ xw_in,
                                               __half* __restrict__ xw_out,
                                               const float* __restrict__ bias,
                                               const float* __restrict__ W) {
    __shared__ float Ws[64 * 64];
    __shared__ float XsT[64][65];
    int tid = threadIdx.x;
    int wrp = tid >> 5, lane = tid & 31;
    int base = blockIdx.x * 64;
    for (int i = tid; i < 4096; i += 256) Ws[i] = W[i];
#pragma unroll 1
    for (int i = 0; i < 8; i++) {
        int r = wrp * 8 + i;
        int n = base + r;
        float a0 = 0.f, a1 = 0.f;
        if (n < NN) gather_node(xw_in, n, lane, bias, a0, a1);
        XsT[lane * 2 + 0][r] = fmaxf(a0, 0.f);
        XsT[lane * 2 + 1][r] = fmaxf(a1, 0.f);
    }
    __syncthreads();
    int tr = tid >> 4, tc = tid & 15;
    float acc[4][4] = {};
#pragma unroll
    for (int k = 0; k < 64; k++) {
        float x0 = XsT[k][tr * 4 + 0];
        float x1 = XsT[k][tr * 4 + 1];
        float x2 = XsT[k][tr * 4 + 2];
        float x3 = XsT[k][tr * 4 + 3];
        float4 wv = *(const float4*)&Ws[k * 64 + tc * 4];
        acc[0][0] += x0 * wv.x; acc[0][1] += x0 * wv.y;
        acc[0][2] += x0 * wv.z; acc[0][3] += x0 * wv.w;
        acc[1][0] += x1 * wv.x; acc[1][1] += x1 * wv.y;
        acc[1][2] += x1 * wv.z; acc[1][3] += x1 * wv.w;
        acc[2][0] += x2 * wv.x; acc[2][1] += x2 * wv.y;
        acc[2][2] += x2 * wv.z; acc[2][3] += x2 * wv.w;
        acc[3][0] += x3 * wv.x; acc[3][1] += x3 * wv.y;
        acc[3][2] += x3 * wv.z; acc[3][3] += x3 * wv.w;
    }
#pragma unroll
    for (int i = 0; i < 4; i++) {
        int row = base + tr * 4 + i;
        if (row < NN)
            store_h4(xw_out, (size_t)row * 64 + tc * 4,
                     acc[i][0], acc[i][1], acc[i][2], acc[i][3]);
    }
}

// ---------------------------------------------------------------------------
// Layer-3 reduced: h2 = relu(agg+self+b2); y = h2 @ M (64x2)
__global__ __launch_bounds__(256) void k_fused_y(const __half* __restrict__ xw_in,
                                                 const float* __restrict__ bias) {
    int wid = (blockIdx.x * blockDim.x + threadIdx.x) >> 5;
    int lane = threadIdx.x & 31;
    if (wid >= NN) return;
    float a0, a1;
    gather_node(xw_in, wid, lane, bias, a0, a1);
    a0 = fmaxf(a0, 0.f);
    a1 = fmaxf(a1, 0.f);
    int j0 = lane * 2, j1 = lane * 2 + 1;
    float y0 = a0 * g_M[j0 * CC + 0] + a1 * g_M[j1 * CC + 0];
    float y1 = a0 * g_M[j0 * CC + 1] + a1 * g_M[j1 * CC + 1];
#pragma unroll
    for (int off = 16; off; off >>= 1) {
        y0 += __shfl_xor_sync(0xffffffffu, y0, off);
        y1 += __shfl_xor_sync(0xffffffffu, y1, off);
    }
    if (lane == 0) *(float2*)&g_y[wid * CC] = make_float2(y0, y1);
}

// ---------------------------------------------------------------------------
// Edge pass in y-space + pool.
__global__ __launch_bounds__(256) void k_edge(const int* __restrict__ batch) {
    int wid = (blockIdx.x * blockDim.x + threadIdx.x) >> 5;
    int lane = threadIdx.x & 31;
    if (wid >= NN) return;
    int n = wid;
    int beg = g_rowptr[n], end = g_rowptr[n + 1];
    float l0 = 0.f, l1 = 0.f;
    for (int cb = beg + lane; cb < end; cb += 32) {
        int2 mv = g_cmeta[cb];
        float v = __int_as_float(mv.y);
        float2 yv = *(const float2*)&g_y[mv.x * CC];
        l0 += v * yv.x;
        l1 += v * yv.y;
    }
#pragma unroll
    for (int off = 16; off; off >>= 1) {
        l0 += __shfl_xor_sync(0xffffffffu, l0, off);
        l1 += __shfl_xor_sync(0xffffffffu, l1, off);
    }
    if (lane == 0) {
        float di = g_dinv[n];
        float sl = 2.0f * di * di;
        float2 yn = *(const float2*)&g_y[n * CC];
        l0 += sl * yn.x;
        l1 += sl * yn.y;
        int g = batch[n];
        atomicAdd(&g_plog[g * CC + 0], l0);
        atomicAdd(&g_plog[g * CC + 1], l1);
    }
}

__global__ __launch_bounds__(256) void k_final(const float* __restrict__ bl,
                                               float* __restrict__ out) {
    int i = blockIdx.x * blockDim.x + threadIdx.x;
    if (i < GG * CC) {
        int g = i / CC, c = i % CC;
        float cnt = g_cnt[g];
        out[i] = (cnt > 0.f) ? g_plog[i] / cnt + g_bWl[c] + bl[c] : bl[c];
    }
}

extern "C" void kernel_launch(void* const* d_in, const int* in_sizes, int n_in,
                              void* d_out, int out_size) {
    const float* x     = (const float*)d_in[0];
    const int*   ei    = (const int*)d_in[1];
    const float* w     = (const float*)d_in[2];
    const int*   batch = (const int*)d_in[3];
    const float* W1    = (const float*)d_in[4];
    const float* b1    = (const float*)d_in[5];
    const float* W2    = (const float*)d_in[6];
    const float* b2    = (const float*)d_in[7];
    const float* W3    = (const float*)d_in[8];
    const float* b3    = (const float*)d_in[9];
    const float* Wl    = (const float*)d_in[10];
    const float* bl    = (const float*)d_in[11];
    float* out = (float*)d_out;

    const int* src = ei;
    const int* dst = ei + EE;

    __half* A;  cudaGetSymbolAddress((void**)&A, g_bufA);
    __half* B;  cudaGetSymbolAddress((void**)&B, g_bufB);

    const int eb = (EE + 255) / 256;
    const int nb = (NN + 255) / 256;
    const int gemm_b = (NN + 63) / 64;
    const int warp_b = (NN * 32 + 255) / 256;

    // CSR + normalization build (reused by all 3 layers)
    k_zero<<<nb, 256>>>(W3, Wl, b3);
    k_deg<<<eb, 256>>>(dst, w);
    k_scanA<<<SCAN_NB, SCAN_T>>>(batch);
    k_scanC<<<SCAN_NB, SCAN_T>>>();
    k_fill<<<eb, 256>>>(src, dst, w);

    // layer 1: xw1 = x @ W1 -> A (fp16)
    k_gemm64<<<gemm_b, 256>>>(x, W1, A);
    // layer 2 fused: h1 = relu(agg(A)+b1); xw2 = h1 @ W2 -> B (fp16)
    k_fused<<<gemm_b, 256>>>(A, B, b1, W2);
    // layer 3 reduced: h2 = relu(agg(B)+b2); y = h2 @ (W3@Wl)
    k_fused_y<<<warp_b, 256>>>(B, b2);
    // edge pass in y-space + pool
    k_edge<<<warp_b, 256>>>(batch);

    k_final<<<(GG * CC + 255) / 256, 256>>>(bl, out);
}

// round 17
// speedup vs baseline: 1.0713x; 1.0151x over previous
#include <cuda_runtime.h>
#include <cuda_fp16.h>

#define NN 100000
#define EE 1000000
#define HH 64
#define GG 512
#define CC 2

#define SCAN_T 512
#define SCAN_NB ((NN + SCAN_T - 1) / SCAN_T)   // 196

// Scratch (device globals; no allocations allowed)
__device__ __half g_bufA[NN * HH];
__device__ __half g_bufB[NN * HH];
__device__ float g_y[NN * CC];
__device__ float g_dinv[NN];
__device__ float g_deg[NN];
__device__ int   g_ecnt[NN];
__device__ int   g_fill[NN];                  // seeded with rowptr by scanC
__device__ int   g_rowptr[NN + 1];
__device__ int2  g_cmeta[EE];                 // (src, dinv[src]*w bits)
__device__ float g_cnt[GG];
__device__ float g_plog[GG * CC];
__device__ float g_M[HH * CC];                // W3 @ Wl
__device__ float g_bWl[CC];                   // b3 @ Wl
__device__ int   g_bsum[SCAN_NB];

// ---------------------------------------------------------------------------
__global__ __launch_bounds__(256) void k_zero(const float* __restrict__ W3,
                                              const float* __restrict__ Wl,
                                              const float* __restrict__ b3) {
    int i = blockIdx.x * blockDim.x + threadIdx.x;
    if (i < NN) { g_deg[i] = 0.f; g_ecnt[i] = 0; }
    if (i < GG) g_cnt[i] = 0.f;
    if (i < GG * CC) g_plog[i] = 0.f;
    if (i == 0) g_rowptr[NN] = EE;            // constant: total edges
    if (blockIdx.x == 0) {
        int t = threadIdx.x;
        if (t < HH * CC) {
            int k = t >> 1, c = t & 1;
            float acc = 0.f;
#pragma unroll
            for (int j = 0; j < HH; j++) acc += W3[k * HH + j] * Wl[j * CC + c];
            g_M[t] = acc;
        } else if (t < HH * CC + CC) {
            int c = t - HH * CC;
            float acc = 0.f;
#pragma unroll
            for (int j = 0; j < HH; j++) acc += b3[j] * Wl[j * CC + c];
            g_bWl[c] = acc;
        }
    }
}

__global__ __launch_bounds__(256) void k_deg(const int* __restrict__ dst,
                                             const float* __restrict__ w) {
    int e = blockIdx.x * blockDim.x + threadIdx.x;
    if (e < EE) {
        int d = dst[e];
        atomicAdd(&g_deg[d], w[e]);
        atomicAdd(&g_ecnt[d], 1);
    }
}

// scanA + dinv + graph node count (fused)
__global__ __launch_bounds__(SCAN_T) void k_scanA(const int* __restrict__ batch) {
    __shared__ int sh[SCAN_T / 32];
    int b = blockIdx.x, t = threadIdx.x;
    int i = b * SCAN_T + t;
    int v = (i < NN) ? g_ecnt[i] : 0;
    if (i < NN) {
        g_dinv[i] = rsqrtf(g_deg[i] + 2.0f);
        atomicAdd(&g_cnt[batch[i]], 1.0f);
    }
    int s = v;
#pragma unroll
    for (int off = 16; off; off >>= 1) s += __shfl_xor_sync(~0u, s, off);
    if ((t & 31) == 0) sh[t >> 5] = s;
    __syncthreads();
    if (t < SCAN_T / 32) {
        int r = sh[t];
#pragma unroll
        for (int off = SCAN_T / 64; off; off >>= 1)
            r += __shfl_xor_sync(0xffffu, r, off);
        if (t == 0) g_bsum[b] = r;
    }
}

// scanC: per-block offset computed in-block from g_bsum, then local scan.
// Also seeds g_fill with the row start (fill cursor).
__global__ __launch_bounds__(SCAN_T) void k_scanC() {
    __shared__ int sh[SCAN_T];
    int b = blockIdx.x, t = threadIdx.x;
    // phase 1: inclusive scan of the 196 block sums
    int bs = (t < SCAN_NB) ? g_bsum[t] : 0;
    sh[t] = bs;
    __syncthreads();
    for (int off = 1; off < SCAN_T; off <<= 1) {
        int u = (t >= off) ? sh[t - off] : 0;
        __syncthreads();
        sh[t] += u;
        __syncthreads();
    }
    int boff = sh[b] - g_bsum[b];             // exclusive offset of this block
    __syncthreads();
    // phase 2: local exclusive scan of ecnt
    int i = b * SCAN_T + t;
    int v = (i < NN) ? g_ecnt[i] : 0;
    sh[t] = v;
    __syncthreads();
    for (int off = 1; off < SCAN_T; off <<= 1) {
        int u = (t >= off) ? sh[t - off] : 0;
        __syncthreads();
        sh[t] += u;
        __syncthreads();
    }
    if (i < NN) {
        int rp = boff + sh[t] - v;
        g_rowptr[i] = rp;
        g_fill[i] = rp;                       // seed fill cursor
    }
}

// fill: pos via single atomic cursor; store (src, dinv[src]*w)
__global__ __launch_bounds__(256) void k_fill(const int* __restrict__ src,
                                              const int* __restrict__ dst,
                                              const float* __restrict__ w) {
    int e = blockIdx.x * blockDim.x + threadIdx.x;
    if (e < EE) {
        int s = src[e], d = dst[e];
        float cv = g_dinv[s] * w[e];          // dinv[dst] hoisted to gather
        int pos = atomicAdd(&g_fill[d], 1);
        g_cmeta[pos] = make_int2(s, __float_as_int(cv));
    }
}

// ---------------------------------------------------------------------------
// Warp-level gather of one node's aggregated row from fp16 xw (2 cols/lane).
// Row sum is scaled by dinv[n] (hoisted), then self-loop + bias added.
__device__ __forceinline__ void gather_node(const __half* __restrict__ xw,
                                            int n, int lane,
                                            const float* __restrict__ bias,
                                            float& a0, float& a1) {
    int beg = g_rowptr[n], end = g_rowptr[n + 1];
    float b0 = 0.f, b1 = 0.f, c0 = 0.f, c1 = 0.f, d0 = 0.f, d1 = 0.f;
    a0 = 0.f; a1 = 0.f;
    for (int cb = beg; cb < end; cb += 32) {
        int m = end - cb; if (m > 32) m = 32;
        int sreg = 0; float vreg = 0.f;
        if (lane < m) {
            int2 mv = g_cmeta[cb + lane];
            sreg = mv.x; vreg = __int_as_float(mv.y);
        }
        int j = 0;
        for (; j + 3 < m; j += 4) {
            int s0 = __shfl_sync(~0u, sreg, j);
            int s1 = __shfl_sync(~0u, sreg, j + 1);
            int s2 = __shfl_sync(~0u, sreg, j + 2);
            int s3 = __shfl_sync(~0u, sreg, j + 3);
            float v0 = __shfl_sync(~0u, vreg, j);
            float v1 = __shfl_sync(~0u, vreg, j + 1);
            float v2 = __shfl_sync(~0u, vreg, j + 2);
            float v3 = __shfl_sync(~0u, vreg, j + 3);
            float2 x0 = __half22float2(*(const __half2*)(xw + (size_t)s0 * 64 + lane * 2));
            float2 x1 = __half22float2(*(const __half2*)(xw + (size_t)s1 * 64 + lane * 2));
            float2 x2 = __half22float2(*(const __half2*)(xw + (size_t)s2 * 64 + lane * 2));
            float2 x3 = __half22float2(*(const __half2*)(xw + (size_t)s3 * 64 + lane * 2));
            a0 += v0 * x0.x; a1 += v0 * x0.y;
            b0 += v1 * x1.x; b1 += v1 * x1.y;
            c0 += v2 * x2.x; c1 += v2 * x2.y;
            d0 += v3 * x3.x; d1 += v3 * x3.y;
        }
        for (; j < m; j++) {
            int s = __shfl_sync(~0u, sreg, j);
            float v = __shfl_sync(~0u, vreg, j);
            float2 xv = __half22float2(*(const __half2*)(xw + (size_t)s * 64 + lane * 2));
            a0 += v * xv.x; a1 += v * xv.y;
        }
    }
    a0 += b0 + c0; a0 += d0;
    a1 += b1 + c1; a1 += d1;
    float di = g_dinv[n];
    float2 xwn = __half22float2(*(const __half2*)(xw + (size_t)n * 64 + lane * 2));
    float2 bb = *(const float2*)(bias + lane * 2);
    // agg = di*(rowsum + 2*di*x[n]) + bias
    a0 = di * (a0 + 2.f * di * xwn.x) + bb.x;
    a1 = di * (a1 + 2.f * di * xwn.y) + bb.y;
}

__device__ __forceinline__ void store_h4(__half* __restrict__ out, size_t off,
                                         float a, float b, float c, float d) {
    __half2 h01 = __floats2half2_rn(a, b);
    __half2 h23 = __floats2half2_rn(c, d);
    uint2 pk;
    pk.x = *reinterpret_cast<unsigned*>(&h01);
    pk.y = *reinterpret_cast<unsigned*>(&h23);
    *reinterpret_cast<uint2*>(out + off) = pk;
}

// ---------------------------------------------------------------------------
// Layer-1 GEMM: out(fp16) = in @ W.
__global__ __launch_bounds__(256) void k_gemm64(const float* __restrict__ in,
                                                const float* __restrict__ W,
                                                __half* __restrict__ out) {
    __shared__ float Ws[64 * 64];
    __shared__ float XsT[64][65];
    int tid = threadIdx.x;
    int base = blockIdx.x * 64;
    for (int i = tid; i < 4096; i += 256) Ws[i] = W[i];
    for (int idx = tid; idx < 4096; idx += 256) {
        int r = idx >> 6, c = idx & 63;
        int row = base + r;
        XsT[c][r] = (row < NN) ? in[row * 64 + c] : 0.f;
    }
    __syncthreads();
    int tr = tid >> 4, tc = tid & 15;
    float acc[4][4] = {};
#pragma unroll
    for (int k = 0; k < 64; k++) {
        float x0 = XsT[k][tr * 4 + 0];
        float x1 = XsT[k][tr * 4 + 1];
        float x2 = XsT[k][tr * 4 + 2];
        float x3 = XsT[k][tr * 4 + 3];
        float4 wv = *(const float4*)&Ws[k * 64 + tc * 4];
        acc[0][0] += x0 * wv.x; acc[0][1] += x0 * wv.y;
        acc[0][2] += x0 * wv.z; acc[0][3] += x0 * wv.w;
        acc[1][0] += x1 * wv.x; acc[1][1] += x1 * wv.y;
        acc[1][2] += x1 * wv.z; acc[1][3] += x1 * wv.w;
        acc[2][0] += x2 * wv.x; acc[2][1] += x2 * wv.y;
        acc[2][2] += x2 * wv.z; acc[2][3] += x2 * wv.w;
        acc[3][0] += x3 * wv.x; acc[3][1] += x3 * wv.y;
        acc[3][2] += x3 * wv.z; acc[3][3] += x3 * wv.w;
    }
#pragma unroll
    for (int i = 0; i < 4; i++) {
        int row = base + tr * 4 + i;
        if (row < NN)
            store_h4(out, (size_t)row * 64 + tc * 4,
                     acc[i][0], acc[i][1], acc[i][2], acc[i][3]);
    }
}

// ---------------------------------------------------------------------------
// Fused: h = relu(agg(xw_in)+self+bias); xw_out(fp16) = h @ W.
__global__ __launch_bounds__(256) void k_fused(const __half* __restrict__ xw_in,
                                               __half* __restrict__ xw_out,
                                               const float* __restrict__ bias,
                                               const float* __restrict__ W) {
    __shared__ float Ws[64 * 64];
    __shared__ float XsT[64][65];
    int tid = threadIdx.x;
    int wrp = tid >> 5, lane = tid & 31;
    int base = blockIdx.x * 64;
    for (int i = tid; i < 4096; i += 256) Ws[i] = W[i];
#pragma unroll 1
    for (int i = 0; i < 8; i++) {
        int r = wrp * 8 + i;
        int n = base + r;
        float a0 = 0.f, a1 = 0.f;
        if (n < NN) gather_node(xw_in, n, lane, bias, a0, a1);
        XsT[lane * 2 + 0][r] = fmaxf(a0, 0.f);
        XsT[lane * 2 + 1][r] = fmaxf(a1, 0.f);
    }
    __syncthreads();
    int tr = tid >> 4, tc = tid & 15;
    float acc[4][4] = {};
#pragma unroll
    for (int k = 0; k < 64; k++) {
        float x0 = XsT[k][tr * 4 + 0];
        float x1 = XsT[k][tr * 4 + 1];
        float x2 = XsT[k][tr * 4 + 2];
        float x3 = XsT[k][tr * 4 + 3];
        float4 wv = *(const float4*)&Ws[k * 64 + tc * 4];
        acc[0][0] += x0 * wv.x; acc[0][1] += x0 * wv.y;
        acc[0][2] += x0 * wv.z; acc[0][3] += x0 * wv.w;
        acc[1][0] += x1 * wv.x; acc[1][1] += x1 * wv.y;
        acc[1][2] += x1 * wv.z; acc[1][3] += x1 * wv.w;
        acc[2][0] += x2 * wv.x; acc[2][1] += x2 * wv.y;
        acc[2][2] += x2 * wv.z; acc[2][3] += x2 * wv.w;
        acc[3][0] += x3 * wv.x; acc[3][1] += x3 * wv.y;
        acc[3][2] += x3 * wv.z; acc[3][3] += x3 * wv.w;
    }
#pragma unroll
    for (int i = 0; i < 4; i++) {
        int row = base + tr * 4 + i;
        if (row < NN)
            store_h4(xw_out, (size_t)row * 64 + tc * 4,
                     acc[i][0], acc[i][1], acc[i][2], acc[i][3]);
    }
}

// ---------------------------------------------------------------------------
// Layer-3 reduced: h2 = relu(agg+self+b2); y = h2 @ M (64x2)
__global__ __launch_bounds__(256) void k_fused_y(const __half* __restrict__ xw_in,
                                                 const float* __restrict__ bias) {
    int wid = (blockIdx.x * blockDim.x + threadIdx.x) >> 5;
    int lane = threadIdx.x & 31;
    if (wid >= NN) return;
    float a0, a1;
    gather_node(xw_in, wid, lane, bias, a0, a1);
    a0 = fmaxf(a0, 0.f);
    a1 = fmaxf(a1, 0.f);
    int j0 = lane * 2, j1 = lane * 2 + 1;
    float y0 = a0 * g_M[j0 * CC + 0] + a1 * g_M[j1 * CC + 0];
    float y1 = a0 * g_M[j0 * CC + 1] + a1 * g_M[j1 * CC + 1];
#pragma unroll
    for (int off = 16; off; off >>= 1) {
        y0 += __shfl_xor_sync(0xffffffffu, y0, off);
        y1 += __shfl_xor_sync(0xffffffffu, y1, off);
    }
    if (lane == 0) *(float2*)&g_y[wid * CC] = make_float2(y0, y1);
}

// ---------------------------------------------------------------------------
// Edge pass in y-space + pool.  cval' = dinv[s]*w; scale row sum by dinv[n].
__global__ __launch_bounds__(256) void k_edge(const int* __restrict__ batch) {
    int wid = (blockIdx.x * blockDim.x + threadIdx.x) >> 5;
    int lane = threadIdx.x & 31;
    if (wid >= NN) return;
    int n = wid;
    int beg = g_rowptr[n], end = g_rowptr[n + 1];
    float l0 = 0.f, l1 = 0.f;
    for (int cb = beg + lane; cb < end; cb += 32) {
        int2 mv = g_cmeta[cb];
        float v = __int_as_float(mv.y);
        float2 yv = *(const float2*)&g_y[mv.x * CC];
        l0 += v * yv.x;
        l1 += v * yv.y;
    }
#pragma unroll
    for (int off = 16; off; off >>= 1) {
        l0 += __shfl_xor_sync(0xffffffffu, l0, off);
        l1 += __shfl_xor_sync(0xffffffffu, l1, off);
    }
    if (lane == 0) {
        float di = g_dinv[n];
        float2 yn = *(const float2*)&g_y[n * CC];
        l0 = di * (l0 + 2.f * di * yn.x);
        l1 = di * (l1 + 2.f * di * yn.y);
        int g = batch[n];
        atomicAdd(&g_plog[g * CC + 0], l0);
        atomicAdd(&g_plog[g * CC + 1], l1);
    }
}

__global__ __launch_bounds__(256) void k_final(const float* __restrict__ bl,
                                               float* __restrict__ out) {
    int i = blockIdx.x * blockDim.x + threadIdx.x;
    if (i < GG * CC) {
        int g = i / CC, c = i % CC;
        float cnt = g_cnt[g];
        out[i] = (cnt > 0.f) ? g_plog[i] / cnt + g_bWl[c] + bl[c] : bl[c];
    }
}

extern "C" void kernel_launch(void* const* d_in, const int* in_sizes, int n_in,
                              void* d_out, int out_size) {
    const float* x     = (const float*)d_in[0];
    const int*   ei    = (const int*)d_in[1];
    const float* w     = (const float*)d_in[2];
    const int*   batch = (const int*)d_in[3];
    const float* W1    = (const float*)d_in[4];
    const float* b1    = (const float*)d_in[5];
    const float* W2    = (const float*)d_in[6];
    const float* b2    = (const float*)d_in[7];
    const float* W3    = (const float*)d_in[8];
    const float* b3    = (const float*)d_in[9];
    const float* Wl    = (const float*)d_in[10];
    const float* bl    = (const float*)d_in[11];
    float* out = (float*)d_out;

    const int* src = ei;
    const int* dst = ei + EE;

    __half* A;  cudaGetSymbolAddress((void**)&A, g_bufA);
    __half* B;  cudaGetSymbolAddress((void**)&B, g_bufB);

    const int eb = (EE + 255) / 256;
    const int nb = (NN + 255) / 256;
    const int gemm_b = (NN + 63) / 64;
    const int warp_b = (NN * 32 + 255) / 256;

    // CSR + normalization build (reused by all 3 layers)
    k_zero<<<nb, 256>>>(W3, Wl, b3);
    k_deg<<<eb, 256>>>(dst, w);
    k_scanA<<<SCAN_NB, SCAN_T>>>(batch);
    k_scanC<<<SCAN_NB, SCAN_T>>>();
    k_fill<<<eb, 256>>>(src, dst, w);

    // layer 1: xw1 = x @ W1 -> A (fp16)
    k_gemm64<<<gemm_b, 256>>>(x, W1, A);
    // layer 2 fused: h1 = relu(agg(A)+b1); xw2 = h1 @ W2 -> B (fp16)
    k_fused<<<gemm_b, 256>>>(A, B, b1, W2);
    // layer 3 reduced: h2 = relu(agg(B)+b2); y = h2 @ (W3@Wl)
    k_fused_y<<<warp_b, 256>>>(B, b2);
    // edge pass in y-space + pool
    k_edge<<<warp_b, 256>>>(batch);

    k_final<<<(GG * CC + 255) / 256, 256>>>(bl, out);
}